// round 4
// baseline (speedup 1.0000x reference)
#include <cuda_runtime.h>
#include <cuda_bf16.h>

// Problem constants (fixed by the dataset)
#define Qn 20000
#define Gn 20000
#define Hn 32          // neighbors per query  (H=32 !)
#define Kn 15          // kernel points
#define Cn 128
#define On 128
#define KC (Kn * Cn)   // 1920

typedef unsigned long long ull;

// Scratch: P[q, k*C + c] intermediate (153.6 MB). Device global per harness rules.
__device__ __align__(256) float g_P[(size_t)Qn * KC];

// ---------------------------------------------------------------------------
// Phase 1: P[q,k,c] = sum_h relu(1-||d||) * feat[nbr[q,h], c]
// One block per query, 128 threads (one per channel c).
// Sparse: with N(0,1) data only ~4.5% of the 480 (h,k) influences are nonzero;
// per-k bitmasks over h let the warp skip zero terms uniformly & deterministically.
// ---------------------------------------------------------------------------
__global__ __launch_bounds__(128) void phase1_kernel(
    const float* __restrict__ qpts,    // [Q,3]
    const float* __restrict__ feats,   // [G,C]
    const float* __restrict__ kpts,    // [K,3]
    const int*   __restrict__ nbr)     // [Q,H]
{
    int q = blockIdx.x;
    int t = threadIdx.x;

    __shared__ float    infl[Hn][Kn + 1];   // [32][16]
    __shared__ int      idx[Hn];
    __shared__ unsigned kmask[Kn];          // bit h set if infl[h][k] > 0
    __shared__ float    qp[3];
    __shared__ float    kp[Kn][3];

    if (t < Hn) idx[t] = nbr[q * Hn + t];
    if (t < 3)  qp[t] = qpts[q * 3 + t];
    if (t >= 64 && t < 64 + Kn * 3) {
        int u = t - 64;
        kp[u / 3][u % 3] = kpts[u];
    }
    __syncthreads();

    // 480 (h,k) influence values across 128 threads (4 passes)
    for (int p = t; p < Hn * Kn; p += 128) {
        int h = p / Kn, k = p % Kn;
        int j = idx[h];
        float dx = qpts[j * 3 + 0] - qp[0] - kp[k][0];
        float dy = qpts[j * 3 + 1] - qp[1] - kp[k][1];
        float dz = qpts[j * 3 + 2] - qp[2] - kp[k][2];
        float d  = sqrtf(fmaf(dx, dx, fmaf(dy, dy, dz * dz)));
        infl[h][k] = fmaxf(1.0f - d, 0.0f);
    }
    __syncthreads();

    // Per-k bitmask of contributing h (threads 0..14)
    if (t < Kn) {
        unsigned m = 0;
#pragma unroll
        for (int h = 0; h < Hn; h++)
            if (infl[h][t] > 0.0f) m |= (1u << h);
        kmask[t] = m;
    }
    __syncthreads();

    // Each thread owns channel c = t. For each k, walk only nonzero h bits.
    int c = t;
    float* Prow = &g_P[(size_t)q * KC];
#pragma unroll
    for (int k = 0; k < Kn; k++) {
        float acc = 0.0f;
        unsigned m = kmask[k];              // uniform across warp -> no divergence
        while (m) {
            int h = __ffs(m) - 1;
            m &= m - 1;
            acc = fmaf(infl[h][k], feats[(size_t)idx[h] * Cn + c], acc);
        }
        Prow[k * Cn + c] = acc;
    }
}

// ---------------------------------------------------------------------------
// Phase 2: out[20000,128] = P[20000,1920] @ Wflat[1920,128]
// SIMT fp32 GEMM using packed fma.rn.f32x2 (2 FMAs per fma-pipe issue).
// BM=32, BN=128, BK=16; 128 threads; thread tile 4(m) x 8(n) as 4x4 f32x2.
// Grid = 625 blocks (exact: 20000 = 32*625).
// ---------------------------------------------------------------------------
#define BM 32
#define BN 128
#define BK 16

__device__ __forceinline__ ull fma2(ull a, ull b, ull c) {
    ull d;
    asm("fma.rn.f32x2 %0, %1, %2, %3;" : "=l"(d) : "l"(a), "l"(b), "l"(c));
    return d;
}

__device__ __forceinline__ ull pack2(float x) {
    unsigned xi = __float_as_uint(x);
    ull d;
    asm("mov.b64 %0, {%1, %1};" : "=l"(d) : "r"(xi));
    return d;
}

__global__ __launch_bounds__(128) void phase2_kernel(
    const float* __restrict__ W,    // [1920,128] row-major (= weights[k,c,o])
    float* __restrict__ out)        // [Q,128]
{
    __shared__ float As[BK][BM];        // A^T tile
    __shared__ float Bs[BK][BN];

    int tid = threadIdx.x;
    int tx = tid & 15;    // n: 8 floats each -> covers 128
    int ty = tid >> 4;    // m: 4 rows each  -> covers 32
    int m0 = blockIdx.x * BM;

    ull acc[4][4];
#pragma unroll
    for (int i = 0; i < 4; i++)
#pragma unroll
        for (int j = 0; j < 4; j++) acc[i][j] = 0ULL;   // two packed +0.0f

    for (int k0 = 0; k0 < KC; k0 += BK) {
        // A tile: 32 rows x 16 cols = 128 float4, one per thread (transposed store)
        {
            int row = tid >> 2, c4 = tid & 3;
            float4 v = *(const float4*)&g_P[(size_t)(m0 + row) * KC + k0 + c4 * 4];
            As[c4 * 4 + 0][row] = v.x;
            As[c4 * 4 + 1][row] = v.y;
            As[c4 * 4 + 2][row] = v.z;
            As[c4 * 4 + 3][row] = v.w;
        }
        // B tile: 16 rows x 128 cols = 512 float4, 4 per thread
#pragma unroll
        for (int it = 0; it < 4; it++) {
            int f   = tid + it * 128;
            int row = f >> 5, c4 = f & 31;
            *(float4*)&Bs[row][c4 * 4] =
                *(const float4*)&W[(size_t)(k0 + row) * On + c4 * 4];
        }
        __syncthreads();

#pragma unroll
        for (int kk = 0; kk < BK; kk++) {
            ull a2[4], b2[4];
#pragma unroll
            for (int i = 0; i < 4; i++) a2[i] = pack2(As[kk][ty * 4 + i]);
            const ull* brow = (const ull*)&Bs[kk][tx * 8];
#pragma unroll
            for (int j = 0; j < 4; j++) b2[j] = brow[j];
#pragma unroll
            for (int i = 0; i < 4; i++)
#pragma unroll
                for (int j = 0; j < 4; j++)
                    acc[i][j] = fma2(a2[i], b2[j], acc[i][j]);
        }
        __syncthreads();
    }

    // Store: each thread writes 4 rows x 8 cols (as 4x 8-byte stores per row)
#pragma unroll
    for (int i = 0; i < 4; i++) {
        int row = m0 + ty * 4 + i;
        float* orow = &out[(size_t)row * On + tx * 8];
#pragma unroll
        for (int j = 0; j < 4; j++)
            *(ull*)&orow[j * 2] = acc[i][j];
    }
}

// ---------------------------------------------------------------------------
// Launch. Input resolution: match by element count (all unique with H=32
// except the two [20000,3] point arrays; query_points comes first in metadata
// dict order, and support_points is unused by the reference math anyway).
// Fallbacks: byte counts, then positional dict order.
// ---------------------------------------------------------------------------
extern "C" void kernel_launch(void* const* d_in, const int* in_sizes, int n_in,
                              void* d_out, int out_size)
{
    const float* qpts  = 0;   // [Q,3]      60000
    const float* feats = 0;   // [G,C]      2560000
    const float* kpts  = 0;   // [K,3]      45
    const float* W     = 0;   // [K,C,O]    245760
    const int*   nbr   = 0;   // [Q,H]      640000

    // Pass 1: element counts
    for (int i = 0; i < n_in; i++) {
        int s = in_sizes[i];
        if      (s == Kn * 3)        { kpts  = (const float*)d_in[i]; }
        else if (s == Kn * Cn * On)  { W     = (const float*)d_in[i]; }
        else if (s == Qn * Hn)       { nbr   = (const int*)  d_in[i]; }
        else if (s == Gn * Cn)       { feats = (const float*)d_in[i]; }
        else if (s == Qn * 3)        { if (!qpts) qpts = (const float*)d_in[i]; }
    }
    // Pass 2: byte counts (in case in_sizes are bytes)
    if (!qpts || !feats || !kpts || !W || !nbr) {
        qpts = feats = kpts = W = 0; nbr = 0;
        for (int i = 0; i < n_in; i++) {
            long long s = in_sizes[i];
            if      (s == 4LL * Kn * 3)       { kpts  = (const float*)d_in[i]; }
            else if (s == 4LL * Kn * Cn * On) { W     = (const float*)d_in[i]; }
            else if (s == 4LL * Qn * Hn)      { nbr   = (const int*)  d_in[i]; }
            else if (s == 4LL * Gn * Cn)      { feats = (const float*)d_in[i]; }
            else if (s == 4LL * Qn * 3)       { if (!qpts) qpts = (const float*)d_in[i]; }
        }
    }
    // Pass 3: positional (setup_inputs dict order)
    if (!qpts || !feats || !kpts || !W || !nbr) {
        qpts  = (const float*)d_in[0];
        feats = (const float*)d_in[2];
        kpts  = (const float*)d_in[3];
        W     = (const float*)d_in[4];
        nbr   = (const int*)  d_in[5];
    }

    float* out = (float*)d_out;

    phase1_kernel<<<Qn, 128>>>(qpts, feats, kpts, nbr);
    phase2_kernel<<<Qn / BM, 128>>>(W, out);
}

// round 6
// speedup vs baseline: 2.4705x; 2.4705x over previous
#include <cuda_runtime.h>
#include <cuda_bf16.h>
#include <cstdint>

// Problem constants (fixed by the dataset)
#define Qn 20000
#define Gn 20000
#define Hn 32          // neighbors per query
#define Kn 15          // kernel points
#define Cn 128
#define On 128
#define KC (Kn * Cn)   // 1920

// Phase-2 GEMM tiling
#define BM 64
#define BN 128
#define BK 64
#define NCH (KC / BK)          // 30 chunks
#define LDT 144                // padded row stride in bytes (64 bf16 + 8 pad)
#define A_TILE_B (BM * LDT)    // 9216
#define B_TILE_B (BN * LDT)    // 18432
#define OFF_ALO  A_TILE_B
#define OFF_BHI  (2 * A_TILE_B)
#define OFF_BLO  (2 * A_TILE_B + B_TILE_B)
#define STAGE_B  (2 * A_TILE_B + 2 * B_TILE_B)   // 55296
#define SMEM_TOTAL (2 * STAGE_B)                  // 110592

// Scratch (device globals per harness rules)
__device__ __align__(256) __nv_bfloat16 g_Phi[(size_t)Qn * KC];
__device__ __align__(256) __nv_bfloat16 g_Plo[(size_t)Qn * KC];
__device__ __align__(256) __nv_bfloat16 g_Wthi[(size_t)On * KC];  // Wt[n][k]
__device__ __align__(256) __nv_bfloat16 g_Wtlo[(size_t)On * KC];

// ---------------------------------------------------------------------------
// PTX helpers (sm_80-era only: compile on base compute_103 target)
// ---------------------------------------------------------------------------
__device__ __forceinline__ uint32_t smem_u32(const void* p) {
    uint32_t a;
    asm("{ .reg .u64 t; cvta.to.shared.u64 t, %1; cvt.u32.u64 %0, t; }" : "=r"(a) : "l"(p));
    return a;
}
__device__ __forceinline__ void cp16(uint32_t dst, const void* src, int sz) {
    asm volatile("cp.async.cg.shared.global [%0], [%1], 16, %2;"
                 :: "r"(dst), "l"(src), "r"(sz) : "memory");
}
#define CP_COMMIT() asm volatile("cp.async.commit_group;" ::: "memory")
#define CP_WAIT(n)  asm volatile("cp.async.wait_group %0;" :: "n"(n) : "memory")

#define LDSM4(R, A)                                                          \
    asm volatile("ldmatrix.sync.aligned.m8n8.x4.shared.b16 {%0,%1,%2,%3}, [%4];" \
                 : "=r"((R)[0]), "=r"((R)[1]), "=r"((R)[2]), "=r"((R)[3]) : "r"(A))

#define MMA(C, A, B)                                                         \
    asm volatile("mma.sync.aligned.m16n8k16.row.col.f32.bf16.bf16.f32 "      \
                 "{%0,%1,%2,%3},{%4,%5,%6,%7},{%8,%9},{%0,%1,%2,%3};"        \
                 : "+f"((C)[0]), "+f"((C)[1]), "+f"((C)[2]), "+f"((C)[3])    \
                 : "r"((A)[0]), "r"((A)[1]), "r"((A)[2]), "r"((A)[3]),       \
                   "r"((B)[0]), "r"((B)[1]))

__device__ __forceinline__ void split_bf16(float v, __nv_bfloat16& hi, __nv_bfloat16& lo) {
    hi = __float2bfloat16(v);
    lo = __float2bfloat16(v - __bfloat162float(hi));
}

// ---------------------------------------------------------------------------
// Phase 1: P[q,k,c] = sum_h relu(1-||d||) * feat[nbr[q,h], c]  -> bf16 hi/lo
// One block per query; sparse h-bitmask contraction (~4.5% nonzero influences).
// ---------------------------------------------------------------------------
__global__ __launch_bounds__(128) void phase1_kernel(
    const float* __restrict__ qpts, const float* __restrict__ feats,
    const float* __restrict__ kpts, const int* __restrict__ nbr)
{
    int q = blockIdx.x;
    int t = threadIdx.x;

    __shared__ float    infl[Hn][Kn + 1];
    __shared__ int      idx[Hn];
    __shared__ unsigned kmask[Kn];
    __shared__ float    qp[3];
    __shared__ float    kp[Kn][3];

    if (t < Hn) idx[t] = nbr[q * Hn + t];
    if (t < 3)  qp[t] = qpts[q * 3 + t];
    if (t >= 64 && t < 64 + Kn * 3) {
        int u = t - 64;
        kp[u / 3][u % 3] = kpts[u];
    }
    __syncthreads();

    for (int p = t; p < Hn * Kn; p += 128) {
        int h = p / Kn, k = p % Kn;
        int j = idx[h];
        float dx = qpts[j * 3 + 0] - qp[0] - kp[k][0];
        float dy = qpts[j * 3 + 1] - qp[1] - kp[k][1];
        float dz = qpts[j * 3 + 2] - qp[2] - kp[k][2];
        float d  = sqrtf(fmaf(dx, dx, fmaf(dy, dy, dz * dz)));
        infl[h][k] = fmaxf(1.0f - d, 0.0f);
    }
    __syncthreads();

    if (t < Kn) {
        unsigned m = 0;
#pragma unroll
        for (int h = 0; h < Hn; h++)
            if (infl[h][t] > 0.0f) m |= (1u << h);
        kmask[t] = m;
    }
    __syncthreads();

    int c = t;
    size_t rowoff = (size_t)q * KC;
#pragma unroll
    for (int k = 0; k < Kn; k++) {
        float acc = 0.0f;
        unsigned m = kmask[k];
        while (m) {
            int h = __ffs(m) - 1;
            m &= m - 1;
            acc = fmaf(infl[h][k], feats[(size_t)idx[h] * Cn + c], acc);
        }
        __nv_bfloat16 hi, lo;
        split_bf16(acc, hi, lo);
        g_Phi[rowoff + k * Cn + c] = hi;
        g_Plo[rowoff + k * Cn + c] = lo;
    }
}

// ---------------------------------------------------------------------------
// W prep: Wt[n][k] = W[k][n] split into bf16 hi/lo. grid (60,4) block (32,8).
// ---------------------------------------------------------------------------
__global__ __launch_bounds__(256) void wprep_kernel(const float* __restrict__ W)
{
    __shared__ float tile[32][33];
    int k0 = blockIdx.x * 32, n0 = blockIdx.y * 32;
    int x = threadIdx.x;
#pragma unroll
    for (int r = threadIdx.y; r < 32; r += 8)
        tile[r][x] = W[(size_t)(k0 + r) * On + n0 + x];
    __syncthreads();
#pragma unroll
    for (int r = threadIdx.y; r < 32; r += 8) {
        float v = tile[x][r];
        __nv_bfloat16 hi, lo;
        split_bf16(v, hi, lo);
        size_t o = (size_t)(n0 + r) * KC + k0 + x;
        g_Wthi[o] = hi;
        g_Wtlo[o] = lo;
    }
}

// ---------------------------------------------------------------------------
// Phase 2: out = (Phi+Plo) @ (Wthi+Wtlo)^T via mma.sync bf16, 3 chains.
// CTA 64x128 tile, 4 warps (warp tile 32x64), BK=64, cp.async double buffer.
// ---------------------------------------------------------------------------
__device__ __forceinline__ void load_chunk(uint32_t sbase, int m0, int k0, int tid)
{
    // A hi/lo: 64 rows x 64 bf16  (512 x 16B per tile, 4 iters of 128 threads)
#pragma unroll
    for (int it = 0; it < 4; it++) {
        int idx = tid + it * 128;
        int r = idx >> 3, j = idx & 7;
        int gm = m0 + r;
        int ok = (gm < Qn);
        size_t go = (size_t)(ok ? gm : 0) * KC + k0 + j * 8;
        uint32_t so = sbase + r * LDT + j * 16;
        int sz = ok ? 16 : 0;
        cp16(so,           g_Phi + go, sz);
        cp16(so + OFF_ALO, g_Plo + go, sz);
    }
    // B hi/lo: 128 rows x 64 bf16 (1024 x 16B per tile, 8 iters)
#pragma unroll
    for (int it = 0; it < 8; it++) {
        int idx = tid + it * 128;
        int r = idx >> 3, j = idx & 7;
        size_t go = (size_t)r * KC + k0 + j * 8;
        uint32_t so = sbase + OFF_BHI + r * LDT + j * 16;
        cp16(so,                       g_Wthi + go, 16);
        cp16(so + (OFF_BLO - OFF_BHI), g_Wtlo + go, 16);
    }
}

__global__ __launch_bounds__(128) void phase2_mma(float* __restrict__ out)
{
    extern __shared__ char smem[];
    const uint32_t s0 = smem_u32(smem);
    const int tid = threadIdx.x;
    const int wid = tid >> 5;
    const int lid = tid & 31;
    const int m0 = blockIdx.x * BM;
    const int wm = wid & 1;        // m half (32 rows)
    const int wn = wid >> 1;       // n half (64 cols)

    float acc[2][8][4];
#pragma unroll
    for (int a = 0; a < 2; a++)
#pragma unroll
        for (int b = 0; b < 8; b++)
#pragma unroll
            for (int c = 0; c < 4; c++) acc[a][b][c] = 0.0f;

    load_chunk(s0, m0, 0, tid);
    CP_COMMIT();

    for (int i = 0; i < NCH; i++) {
        if (i + 1 < NCH) {
            load_chunk(s0 + ((i + 1) & 1) * STAGE_B, m0, (i + 1) * BK, tid);
            CP_COMMIT();
            CP_WAIT(1);
        } else {
            CP_WAIT(0);
        }
        __syncthreads();

        const uint32_t sb = s0 + (i & 1) * STAGE_B;
#pragma unroll
        for (int kst = 0; kst < 4; kst++) {
            const uint32_t kb = kst * 32 + (lid >> 4) * 16;   // byte offset within row
            uint32_t afh[2][4], afl[2][4];
#pragma unroll
            for (int mt = 0; mt < 2; mt++) {
                int row = wm * 32 + mt * 16 + (lid & 15);
                uint32_t off = row * LDT + kb;
                LDSM4(afh[mt], sb + off);
                LDSM4(afl[mt], sb + OFF_ALO + off);
            }
            uint32_t bfh[8][2], bfl[8][2];
#pragma unroll
            for (int p = 0; p < 4; p++) {
                int n = wn * 64 + p * 16 + (lid & 15);
                uint32_t off = n * LDT + kb;
                uint32_t r[4];
                LDSM4(r, sb + OFF_BHI + off);
                bfh[2 * p][0] = r[0]; bfh[2 * p][1] = r[2];
                bfh[2 * p + 1][0] = r[1]; bfh[2 * p + 1][1] = r[3];
                LDSM4(r, sb + OFF_BLO + off);
                bfl[2 * p][0] = r[0]; bfl[2 * p][1] = r[2];
                bfl[2 * p + 1][0] = r[1]; bfl[2 * p + 1][1] = r[3];
            }
#pragma unroll
            for (int mt = 0; mt < 2; mt++)
#pragma unroll
                for (int nt = 0; nt < 8; nt++) {
                    MMA(acc[mt][nt], afh[mt], bfh[nt]);
                    MMA(acc[mt][nt], afh[mt], bfl[nt]);
                    MMA(acc[mt][nt], afl[mt], bfh[nt]);
                }
        }
        __syncthreads();
    }

    // Epilogue
    int g = lid >> 2, tg = lid & 3;
#pragma unroll
    for (int mt = 0; mt < 2; mt++) {
        int r0 = m0 + wm * 32 + mt * 16 + g;
#pragma unroll
        for (int nt = 0; nt < 8; nt++) {
            int col = wn * 64 + nt * 8 + 2 * tg;
            if (r0 < Qn)
                *(float2*)&out[(size_t)r0 * On + col] =
                    make_float2(acc[mt][nt][0], acc[mt][nt][1]);
            if (r0 + 8 < Qn)
                *(float2*)&out[(size_t)(r0 + 8) * On + col] =
                    make_float2(acc[mt][nt][2], acc[mt][nt][3]);
        }
    }
}

// ---------------------------------------------------------------------------
// Launch
// ---------------------------------------------------------------------------
extern "C" void kernel_launch(void* const* d_in, const int* in_sizes, int n_in,
                              void* d_out, int out_size)
{
    const float* qpts  = 0;
    const float* feats = 0;
    const float* kpts  = 0;
    const float* W     = 0;
    const int*   nbr   = 0;

    for (int i = 0; i < n_in; i++) {
        int s = in_sizes[i];
        if      (s == Kn * 3)        { kpts  = (const float*)d_in[i]; }
        else if (s == Kn * Cn * On)  { W     = (const float*)d_in[i]; }
        else if (s == Qn * Hn)       { nbr   = (const int*)  d_in[i]; }
        else if (s == Gn * Cn)       { feats = (const float*)d_in[i]; }
        else if (s == Qn * 3)        { if (!qpts) qpts = (const float*)d_in[i]; }
    }
    if (!qpts || !feats || !kpts || !W || !nbr) {   // positional fallback
        qpts  = (const float*)d_in[0];
        feats = (const float*)d_in[2];
        kpts  = (const float*)d_in[3];
        W     = (const float*)d_in[4];
        nbr   = (const int*)  d_in[5];
    }
    float* out = (float*)d_out;

    static bool attr_set = false;
    if (!attr_set) {
        cudaFuncSetAttribute(phase2_mma,
                             cudaFuncAttributeMaxDynamicSharedMemorySize, SMEM_TOTAL);
        attr_set = true;
    }

    phase1_kernel<<<Qn, 128>>>(qpts, feats, kpts, nbr);
    wprep_kernel<<<dim3(KC / 32, On / 32), dim3(32, 8)>>>(W);
    phase2_mma<<<(Qn + BM - 1) / BM, 128, SMEM_TOTAL>>>(out);
}